// round 8
// baseline (speedup 1.0000x reference)
#include <cuda_runtime.h>
#include <cuda_bf16.h>
#include <cstdint>

// Embedding gather via TMA bulk copies: out[row,:] = table[token_ids[row],:]
//   table: [50257, 768] fp32, ids: [16384] int64|int32 (auto), out 16384x768.
//
// R6 finding: four LDG-based variants plateau at ~15.5us with every unit
// <40% busy -> the per-access LSU/L1tex path itself is binding. Switch the
// datapath entirely: cp.async.bulk global->shared->global, single elected
// thread per CTA, 8-slot smem ring, 6 loads in flight, bulk_group stores.
// No RF traffic, no L1, ~126KB outstanding per SM.
// (R7 resubmit: container infra failure; pipeline audited for hangs --
// parity, slot-reuse WAR via wait_group.read<2>, alignment, exit drain.)

#define VOCAB        50257
#define D_MODEL      768
#define ROW_BYTES    3072
#define N_ROWS       16384
#define ROWS_PER_CTA 16
#define GRID_CTAS    (N_ROWS / ROWS_PER_CTA)   // 1024
#define NS           8                          // smem ring slots
#define AHEAD        6                          // loads in flight

__device__ int g_tokens[N_ROWS];

// ---- width-detect + convert (verdict uniform across blocks) ----
__global__ void convert_ids_kernel(const unsigned long long* __restrict__ ids_u64) {
    bool is64 = true;
    #pragma unroll 4
    for (int i = threadIdx.x & 127; i < 512; i += 128) {
        if (ids_u64[i] >= (unsigned long long)VOCAB) is64 = false;
    }
    is64 = __all_sync(0xFFFFFFFFu, is64);

    const int idx = blockIdx.x * blockDim.x + threadIdx.x;
    if (idx < N_ROWS) {
        int tok;
        if (is64) tok = (int)((const long long*)ids_u64)[idx];
        else      tok = ((const int*)ids_u64)[idx];
        g_tokens[idx] = tok;
    }
}

// ---- PTX helpers ----
__device__ __forceinline__ uint32_t smem_u32(const void* p) {
    uint32_t a;
    asm("{ .reg .u64 t; cvta.to.shared.u64 t, %1; cvt.u32.u64 %0, t; }"
        : "=r"(a) : "l"(p));
    return a;
}
__device__ __forceinline__ void mbar_init(uint32_t mbar, uint32_t cnt) {
    asm volatile("mbarrier.init.shared.b64 [%0], %1;" :: "r"(mbar), "r"(cnt) : "memory");
}
__device__ __forceinline__ void mbar_expect_tx(uint32_t mbar, uint32_t bytes) {
    asm volatile("mbarrier.arrive.expect_tx.shared.b64 _, [%0], %1;"
                 :: "r"(mbar), "r"(bytes) : "memory");
}
__device__ __forceinline__ void mbar_wait(uint32_t mbar, uint32_t parity) {
    asm volatile(
        "{\n\t.reg .pred P;\n\t"
        "WL_%=:\n\t"
        "mbarrier.try_wait.parity.shared.b64 P, [%0], %1, 0x989680;\n\t"
        "@P bra.uni WD_%=;\n\t"
        "bra.uni WL_%=;\n\t"
        "WD_%=:\n\t}"
        :: "r"(mbar), "r"(parity) : "memory");
}
__device__ __forceinline__ void bulk_ld(uint32_t smem_dst, const void* gmem_src,
                                        uint32_t bytes, uint32_t mbar) {
    asm volatile(
        "cp.async.bulk.shared::cta.global.mbarrier::complete_tx::bytes [%0], [%1], %2, [%3];"
        :: "r"(smem_dst), "l"(gmem_src), "r"(bytes), "r"(mbar) : "memory");
}
__device__ __forceinline__ void bulk_st(void* gmem_dst, uint32_t smem_src, uint32_t bytes) {
    asm volatile(
        "cp.async.bulk.global.shared::cta.bulk_group [%0], [%1], %2;"
        :: "l"(gmem_dst), "r"(smem_src), "r"(bytes) : "memory");
}
__device__ __forceinline__ void bulk_commit() {
    asm volatile("cp.async.bulk.commit_group;" ::: "memory");
}
template <int N> __device__ __forceinline__ void bulk_wait_read() {
    asm volatile("cp.async.bulk.wait_group.read %0;" :: "n"(N) : "memory");
}
template <int N> __device__ __forceinline__ void bulk_wait() {
    asm volatile("cp.async.bulk.wait_group %0;" :: "n"(N) : "memory");
}

// ---- TMA pipeline kernel: 16 rows/CTA, single driver thread ----
__global__ __launch_bounds__(32)
void embedding_tma_kernel(const char* __restrict__ table, char* __restrict__ out) {
    __shared__ __align__(1024) char buf[NS * ROW_BYTES];
    __shared__ __align__(8) unsigned long long mbar_store[NS];
    __shared__ int toks[ROWS_PER_CTA];

    const int row0 = blockIdx.x * ROWS_PER_CTA;
    const int t = threadIdx.x;

    if (t < ROWS_PER_CTA) toks[t] = g_tokens[row0 + t];
    if (t < NS) mbar_init(smem_u32(&mbar_store[t]), 1);
    __syncthreads();

    if (t == 0) {
        const uint32_t buf0 = smem_u32(buf);
        const uint32_t mb0  = smem_u32(mbar_store);

        // prologue: AHEAD loads in flight
        #pragma unroll
        for (int s = 0; s < AHEAD; s++) {
            mbar_expect_tx(mb0 + 8u * s, ROW_BYTES);
            bulk_ld(buf0 + (uint32_t)s * ROW_BYTES,
                    table + (long long)toks[s] * ROW_BYTES,
                    ROW_BYTES, mb0 + 8u * s);
        }

        #pragma unroll 1
        for (int i = 0; i < ROWS_PER_CTA; i++) {
            const int s = i & (NS - 1);
            mbar_wait(mb0 + 8u * s, (i >> 3) & 1);          // load i landed
            bulk_st(out + (long long)(row0 + i) * ROW_BYTES,
                    buf0 + (uint32_t)s * ROW_BYTES, ROW_BYTES);
            bulk_commit();

            const int nr = i + AHEAD;                        // refill slot
            if (nr < ROWS_PER_CTA) {
                // slot nr%NS last held row nr-NS = i-2; wait_group.read<2>
                // leaves at most stores {i-1, i} unread -> i-2 is read.
                bulk_wait_read<2>();
                const int s2 = nr & (NS - 1);
                mbar_expect_tx(mb0 + 8u * s2, ROW_BYTES);
                bulk_ld(buf0 + (uint32_t)s2 * ROW_BYTES,
                        table + (long long)toks[nr] * ROW_BYTES,
                        ROW_BYTES, mb0 + 8u * s2);
            }
        }
        bulk_wait<0>();   // all stores complete before CTA exit
    }
}

extern "C" void kernel_launch(void* const* d_in, const int* in_sizes, int n_in,
                              void* d_out, int out_size) {
    const void* ids   = d_in[0];
    const char* table = (const char*)d_in[1];
    char*       out   = (char*)d_out;

    convert_ids_kernel<<<N_ROWS / 256, 256>>>((const unsigned long long*)ids);
    embedding_tma_kernel<<<GRID_CTAS, 32>>>(table, out);
}